// round 6
// baseline (speedup 1.0000x reference)
#include <cuda_runtime.h>
#include <math.h>
#include <stdint.h>

#define BSZ 32
#define SEQ 2048
#define DIM 512
#define DGLU 1024
#define MROWS (BSZ * SEQ)
#define SCAN_TS 32
#define SCAN_CH (SEQ / SCAN_TS)

#define SROW 20
#define TILEF (128 * SROW)
#define STAGEF (2 * TILEF)
#define NSTAGE 4
#define SMEM_BYTES (NSTAGE * STAGEF * 4)   // 81920

__device__ float g_bufA[(size_t)MROWS * DIM];
__device__ float g_bufB[(size_t)MROWS * DIM];
__device__ float g_bufC[(size_t)MROWS * DIM];
__device__ float g_bufD[(size_t)MROWS * DIM];
__device__ float g_bufE[(size_t)MROWS * DGLU];
__device__ float g_bufF[(size_t)MROWS * DGLU];
__device__ float g_WT[2623488];   // 7 transposed weights + concat bias

__device__ __forceinline__ float sigmoidf_(float v) { return 1.f / (1.f + expf(-v)); }
__device__ __forceinline__ float rnd32(float f) {
    uint32_t u; asm("cvt.rna.tf32.f32 %0, %1;" : "=r"(u) : "f"(f));
    return __uint_as_float(u);
}

enum { MODE_PLAIN = 0, MODE_GLU = 1, MODE_TRI = 2 };

__device__ __forceinline__ void mma_tf32(float* d, const uint32_t* a, const uint32_t* b) {
    asm volatile("mma.sync.aligned.m16n8k8.row.col.f32.tf32.tf32.f32 "
                 "{%0,%1,%2,%3}, {%4,%5,%6,%7}, {%8,%9}, {%0,%1,%2,%3};"
                 : "+f"(d[0]), "+f"(d[1]), "+f"(d[2]), "+f"(d[3])
                 : "r"(a[0]), "r"(a[1]), "r"(a[2]), "r"(a[3]), "r"(b[0]), "r"(b[1]));
}
__device__ __forceinline__ void cpasync16(uint32_t dst, const void* src) {
    asm volatile("cp.async.cg.shared.global [%0], [%1], 16;" :: "r"(dst), "l"(src));
}
__device__ __forceinline__ uint32_t smem_u32(const void* p) {
    uint32_t a;
    asm("{ .reg .u64 t; cvta.to.shared.u64 t, %1; cvt.u32.u64 %0, t; }" : "=r"(a) : "l"(p));
    return a;
}

__device__ __forceinline__ void stage_in(uint32_t smem_stage_u, const float* Ab, const float* Bb,
                                         int K, int kc, int tid) {
#pragma unroll
    for (int i = 0; i < 8; i++) {
        const int idx = tid + i * 128;          // 0..1023
        const int mat = idx >> 9;               // 0=A, 1=B
        const int r   = (idx >> 2) & 127;
        const int c4  = idx & 3;
        const float* src = (mat ? Bb : Ab) + (size_t)r * K + kc * 16 + c4 * 4;
        const uint32_t dst = smem_stage_u + (uint32_t)(mat * TILEF + r * SROW + c4 * 4) * 4u;
        cpasync16(dst, src);
    }
}

// C[M,N] = epilogue(A[M,K] @ WT[N,K]^T + bias)
// WT rows are k-permuted per 8-group: pos 2c <- k=c, 2c+1 <- k=c+4
// 128 threads, 4 warps in 2x2, 64x64 warp tiles.
template <int MODE, bool ROUND>
__global__ __launch_bounds__(128, 2)
void tc_gemm(const float* __restrict__ A, const float* __restrict__ WT,
             const float* __restrict__ bias, float* __restrict__ C,
             float* __restrict__ C1, float* __restrict__ C2,
             const float* __restrict__ aux, const float* __restrict__ lbp, int N, int K)
{
    extern __shared__ float sm[];

    const int tid = threadIdx.x, wid = tid >> 5, lane = tid & 31;
    const int g = lane >> 2, cc = lane & 3;
    const int bm = blockIdx.y * 128;
    const int wm = (wid >> 1) * 64, wn = (wid & 1) * 64;
    const uint32_t sm_u = smem_u32(sm);

    const float* Ab = A + (size_t)bm * K;
    const float* Bb = WT + (size_t)blockIdx.x * 128 * K;
    const int NK = K >> 4;

    float acc[4][8][4];
#pragma unroll
    for (int mf = 0; mf < 4; mf++)
#pragma unroll
        for (int nf = 0; nf < 8; nf++)
#pragma unroll
            for (int k = 0; k < 4; k++) acc[mf][nf][k] = 0.f;

#pragma unroll
    for (int s = 0; s < 3; s++) {
        stage_in(sm_u + s * STAGEF * 4, Ab, Bb, K, s, tid);
        asm volatile("cp.async.commit_group;");
    }

    for (int kc = 0; kc < NK; kc++) {
        asm volatile("cp.async.wait_group 2;");
        __syncthreads();
        if (kc + 3 < NK)
            stage_in(sm_u + ((kc + 3) & 3) * STAGEF * 4, Ab, Bb, K, kc + 3, tid);
        asm volatile("cp.async.commit_group;");

        const float* As = sm + (kc & 3) * STAGEF;
        const float* Bs = As + TILEF;
#pragma unroll
        for (int ks = 0; ks < 2; ks++) {
            uint32_t af[4][4], bf[8][2];
#pragma unroll
            for (int mf = 0; mf < 4; mf++) {
                const float* p = As + (wm + mf * 16 + g) * SROW + ks * 8 + cc;
                af[mf][0] = __float_as_uint(p[0]);
                af[mf][1] = __float_as_uint(p[8 * SROW]);
                af[mf][2] = __float_as_uint(p[4]);
                af[mf][3] = __float_as_uint(p[8 * SROW + 4]);
            }
#pragma unroll
            for (int nf = 0; nf < 8; nf++) {
                // permuted B: one 8-byte load gives (k=cc, k=cc+4)
                const float2 q = *(const float2*)(Bs + (wn + nf * 8 + g) * SROW + ks * 8 + cc * 2);
                bf[nf][0] = __float_as_uint(q.x);
                bf[nf][1] = __float_as_uint(q.y);
            }
#pragma unroll
            for (int mf = 0; mf < 4; mf++)
#pragma unroll
                for (int nf = 0; nf < 8; nf++)
                    mma_tf32(acc[mf][nf], af[mf], bf[nf]);
        }
        __syncthreads();
    }

    // epilogue
    int seg = 0, bnl = blockIdx.x * 128;
    float* Cout = C;
    float lb = 0.f;
    if (MODE == MODE_TRI) {
        seg = blockIdx.x >> 2;
        bnl = (blockIdx.x & 3) * 128;
        Cout = (seg == 0) ? C : (seg == 1 ? C1 : C2);
        if (seg == 0) lb = __ldg(lbp);
    }

#pragma unroll
    for (int mf = 0; mf < 4; mf++) {
#pragma unroll
        for (int half = 0; half < 2; half++) {
            const int row = bm + wm + mf * 16 + g + half * 8;
            float* Crow = Cout + (size_t)row * N;
            const float* Arow = (MODE == MODE_GLU) ? aux + (size_t)row * N : nullptr;
#pragma unroll
            for (int nf = 0; nf < 8; nf++) {
                const int col = bnl + wn + nf * 8 + cc * 2;
                const float2 bb = *(const float2*)&bias[blockIdx.x * 128 + wn + nf * 8 + cc * 2];
                float v0 = acc[mf][nf][half * 2 + 0] + bb.x;
                float v1 = acc[mf][nf][half * 2 + 1] + bb.y;
                float o0 = v0, o1 = v1;
                if (MODE == MODE_TRI) {
                    if (seg == 0) {
                        o0 = lb + (1.f - lb) * sigmoidf_(v0);
                        o1 = lb + (1.f - lb) * sigmoidf_(v1);
                    } else if (seg == 2) {
                        o0 = sigmoidf_(v0); o1 = sigmoidf_(v1);
                    } // seg 1: raw i, silu applied in scan
                } else if (MODE == MODE_GLU) {
                    const float2 ax = *(const float2*)(Arow + col);
                    o0 = (v0 * sigmoidf_(v0)) * ax.x;
                    o1 = (v1 * sigmoidf_(v1)) * ax.y;
                }
                if (ROUND) { o0 = rnd32(o0); o1 = rnd32(o1); }
                float2 o; o.x = o0; o.y = o1;
                *(float2*)(Crow + col) = o;
            }
        }
    }
}

// dst[n*K + permute(k)] = round_tf32(src[k*N+n]); per-8 k-group perm: c -> 2c, c+4 -> 2c+1
__global__ void transpose_w(const float* __restrict__ src, float* __restrict__ dst, int K, int N) {
    __shared__ float tile[32][33];
    const int n0 = blockIdx.x * 32, k0 = blockIdx.y * 32;
    for (int i = threadIdx.y; i < 32; i += 8)
        tile[i][threadIdx.x] = src[(size_t)(k0 + i) * N + n0 + threadIdx.x];
    __syncthreads();
    const int tx = threadIdx.x;
    const int grp = tx >> 3, r = tx & 7;
    const int pk = (grp << 3) + ((r < 4) ? (r << 1) : (((r - 4) << 1) + 1));
    for (int i = threadIdx.y; i < 32; i += 8)
        dst[(size_t)(n0 + i) * K + k0 + pk] = rnd32(tile[tx][i]);
}

__global__ void round_x(const float* __restrict__ src, float* __restrict__ dst) {
    const size_t i = (size_t)blockIdx.x * blockDim.x + threadIdx.x;
    float4 v = *(const float4*)(src + i * 4);
    v.x = rnd32(v.x); v.y = rnd32(v.y); v.z = rnd32(v.z); v.w = rnd32(v.w);
    *(float4*)(dst + i * 4) = v;
}

__global__ void bias_cat(const float* __restrict__ b0, const float* __restrict__ b1,
                         const float* __restrict__ b2, float* __restrict__ dst) {
    const int i = blockIdx.x * blockDim.x + threadIdx.x;
    if (i < DIM) dst[i] = b0[i];
    else if (i < 2 * DIM) dst[i] = b1[i - DIM];
    else if (i < 3 * DIM) dst[i] = b2[i - 2 * DIM];
}

// pass1: u = (1-lam)*silu(iraw) computed on the fly
__global__ __launch_bounds__(512)
void scan_pass1(const float* __restrict__ lam, const float* __restrict__ iraw,
                float* __restrict__ lF, float* __restrict__ lB,
                float* __restrict__ prod, float* __restrict__ lastF, float* __restrict__ lastB)
{
    const int b = blockIdx.x >> 6, ch = blockIdx.x & 63;
    const int d = threadIdx.x;
    const size_t base = ((size_t)b * SEQ + ch * SCAN_TS) * DIM + d;
    float hf = 0.f, p = 1.f;
#pragma unroll 4
    for (int t = 0; t < SCAN_TS; t++) {
        const size_t ix = base + (size_t)t * DIM;
        const float l = lam[ix], iv = iraw[ix];
        const float u = (1.f - l) * (iv * sigmoidf_(iv));
        hf = fmaf(l, hf, u); p *= l; lF[ix] = hf;
    }
    float hb = 0.f;
#pragma unroll 4
    for (int t = SCAN_TS - 1; t >= 0; t--) {
        const size_t ix = base + (size_t)t * DIM;
        const float l = lam[ix], iv = iraw[ix];
        const float u = (1.f - l) * (iv * sigmoidf_(iv));
        hb = fmaf(l, hb, u); lB[ix] = hb;
    }
    const int ci = (b * SCAN_CH + ch) * DIM + d;
    prod[ci] = p; lastF[ci] = hf; lastB[ci] = hb;
}

__global__ void scan_pass2(const float* __restrict__ prod, const float* __restrict__ lastF,
                           const float* __restrict__ lastB, float* __restrict__ CF, float* __restrict__ CB)
{
    const int c = blockIdx.x * blockDim.x + threadIdx.x;
    if (c >= BSZ * DIM) return;
    const int b = c >> 9, d = c & 511;
    float cf = 0.f;
    for (int ch = 0; ch < SCAN_CH; ch++) {
        const int i = (b * SCAN_CH + ch) * DIM + d;
        CF[i] = cf; cf = fmaf(prod[i], cf, lastF[i]);
    }
    float cb = 0.f;
    for (int ch = SCAN_CH - 1; ch >= 0; ch--) {
        const int i = (b * SCAN_CH + ch) * DIM + d;
        CB[i] = cb; cb = fmaf(prod[i], cb, lastB[i]);
    }
}

// pass3 fused with rmsnorm*gate: out = round_tf32(rmsnorm(h) * g)
__global__ __launch_bounds__(512)
void scan_pass3_rms(const float* __restrict__ lam, const float* __restrict__ lF,
                    const float* __restrict__ lB, const float* __restrict__ CF,
                    const float* __restrict__ CB, const float* __restrict__ g,
                    float* __restrict__ out)
{
    __shared__ float red[16];
    const int b = blockIdx.x >> 6, ch = blockIdx.x & 63;
    const int d = threadIdx.x, wid = d >> 5, lane = d & 31;
    const size_t base = ((size_t)b * SEQ + ch * SCAN_TS) * DIM + d;
    const int ci = (b * SCAN_CH + ch) * DIM + d;
    const float cf = CF[ci], cb = CB[ci];
    float vals[SCAN_TS];
    float p = 1.f;
#pragma unroll
    for (int t = 0; t < SCAN_TS; t++) {
        const size_t ix = base + (size_t)t * DIM;
        p *= lam[ix];
        vals[t] = fmaf(cf, p, lF[ix]);
    }
    float q = 1.f;
#pragma unroll
    for (int t = SCAN_TS - 1; t >= 0; t--) {
        const size_t ix = base + (size_t)t * DIM;
        q *= lam[ix];
        vals[t] += fmaf(cb, q, lB[ix]);
    }
#pragma unroll 1
    for (int t = 0; t < SCAN_TS; t++) {
        const size_t ix = base + (size_t)t * DIM;
        const float v = vals[t];
        float ss = v * v;
#pragma unroll
        for (int o = 16; o > 0; o >>= 1) ss += __shfl_xor_sync(0xffffffffu, ss, o);
        if (lane == 0) red[wid] = ss;
        __syncthreads();
        float tot = 0.f;
#pragma unroll
        for (int w = 0; w < 16; w++) tot += red[w];
        const float scale = rsqrtf(tot * (1.f / DIM) + 1e-6f);
        out[ix] = rnd32(v * scale * g[ix]);
        __syncthreads();
    }
}

// out = resid + LN(y)*gam + bet ; optional rounded copy
__global__ void ln_add(const float* __restrict__ y, const float* __restrict__ resid,
                       const float* __restrict__ gam, const float* __restrict__ bet,
                       float* __restrict__ out, float* __restrict__ outR) {
    const int row = blockIdx.x * 8 + (threadIdx.x >> 5), lane = threadIdx.x & 31;
    const float* yr = y + (size_t)row * DIM;
    float4 v[4]; float s1 = 0.f, s2 = 0.f;
#pragma unroll
    for (int i = 0; i < 4; i++) {
        v[i] = *(const float4*)(yr + i * 128 + lane * 4);
        s1 += v[i].x + v[i].y + v[i].z + v[i].w;
        s2 += v[i].x * v[i].x + v[i].y * v[i].y + v[i].z * v[i].z + v[i].w * v[i].w;
    }
#pragma unroll
    for (int o = 16; o > 0; o >>= 1) {
        s1 += __shfl_xor_sync(0xffffffffu, s1, o);
        s2 += __shfl_xor_sync(0xffffffffu, s2, o);
    }
    const float mean = s1 * (1.f / DIM);
    const float inv = rsqrtf(s2 * (1.f / DIM) - mean * mean + 1e-5f);
    const float* rr = resid + (size_t)row * DIM;
    float* outr = out + (size_t)row * DIM;
    float* outr2 = outR ? outR + (size_t)row * DIM : nullptr;
#pragma unroll
    for (int i = 0; i < 4; i++) {
        const int col = i * 128 + lane * 4;
        float4 gv = *(const float4*)(gam + col);
        float4 bv = *(const float4*)(bet + col);
        float4 xv = *(const float4*)(rr + col);
        float4 r;
        r.x = xv.x + (v[i].x - mean) * inv * gv.x + bv.x;
        r.y = xv.y + (v[i].y - mean) * inv * gv.y + bv.y;
        r.z = xv.z + (v[i].z - mean) * inv * gv.z + bv.z;
        r.w = xv.w + (v[i].w - mean) * inv * gv.w + bv.w;
        *(float4*)(outr + col) = r;
        if (outr2) {
            float4 r2;
            r2.x = rnd32(r.x); r2.y = rnd32(r.y); r2.z = rnd32(r.z); r2.w = rnd32(r.w);
            *(float4*)(outr2 + col) = r2;
        }
    }
}

extern "C" void kernel_launch(void* const* d_in, const int* in_sizes, int n_in,
                              void* d_out, int out_size)
{
    const float* x = (const float*)d_in[0];
    const float* lbp = (const float*)d_in[1];
    const float* Wi = (const float*)d_in[2];  const float* bi = (const float*)d_in[3];
    const float* Wf = (const float*)d_in[4];  const float* bf = (const float*)d_in[5];
    const float* Wg = (const float*)d_in[6];  const float* bg = (const float*)d_in[7];
    const float* Wo = (const float*)d_in[8];  const float* bo = (const float*)d_in[9];
    const float* tn_g = (const float*)d_in[10]; const float* tn_b = (const float*)d_in[11];
    const float* fn_g = (const float*)d_in[12]; const float* fn_b = (const float*)d_in[13];
    const float* W1 = (const float*)d_in[14]; const float* b1 = (const float*)d_in[15];
    const float* W2 = (const float*)d_in[16]; const float* b2 = (const float*)d_in[17];
    const float* W3 = (const float*)d_in[18]; const float* b3 = (const float*)d_in[19];
    float* out = (float*)d_out;

    float *bA, *bB, *bC, *bD, *bE, *bF, *wt;
    cudaGetSymbolAddress((void**)&bA, g_bufA);
    cudaGetSymbolAddress((void**)&bB, g_bufB);
    cudaGetSymbolAddress((void**)&bC, g_bufC);
    cudaGetSymbolAddress((void**)&bD, g_bufD);
    cudaGetSymbolAddress((void**)&bE, g_bufE);
    cudaGetSymbolAddress((void**)&bF, g_bufF);
    cudaGetSymbolAddress((void**)&wt, g_WT);

    float* WfT = wt;                    // rows 0-511 of merged
    float* WiT = wt + 262144;           // rows 512-1023
    float* WgT = wt + 524288;           // rows 1024-1535
    float* WoT = wt + 786432;
    float* W1T = wt + 1048576;
    float* W2T = wt + 1572864;
    float* W3T = wt + 2097152;
    float* bcat = wt + 2621440;         // 1536 floats

    float* lF = bE;
    float* lB = bF;
    float* prod  = bE + (size_t)MROWS * DIM;
    float* lastF = prod + (size_t)BSZ * SCAN_CH * DIM;
    float* lastB = lastF + (size_t)BSZ * SCAN_CH * DIM;
    float* CF = bF + (size_t)MROWS * DIM;
    float* CB = CF + (size_t)BSZ * SCAN_CH * DIM;

    cudaFuncSetAttribute(tc_gemm<MODE_TRI,   false>, cudaFuncAttributeMaxDynamicSharedMemorySize, SMEM_BYTES);
    cudaFuncSetAttribute(tc_gemm<MODE_PLAIN, false>, cudaFuncAttributeMaxDynamicSharedMemorySize, SMEM_BYTES);
    cudaFuncSetAttribute(tc_gemm<MODE_GLU,   true>,  cudaFuncAttributeMaxDynamicSharedMemorySize, SMEM_BYTES);

    dim3 tb(32, 8);
    round_x<<<32768, 256>>>(x, bD);
    transpose_w<<<dim3(16, 16), tb>>>(Wf, WfT, DIM, DIM);
    transpose_w<<<dim3(16, 16), tb>>>(Wi, WiT, DIM, DIM);
    transpose_w<<<dim3(16, 16), tb>>>(Wg, WgT, DIM, DIM);
    transpose_w<<<dim3(16, 16), tb>>>(Wo, WoT, DIM, DIM);
    transpose_w<<<dim3(32, 16), tb>>>(W1, W1T, DIM, DGLU);
    transpose_w<<<dim3(32, 16), tb>>>(W2, W2T, DIM, DGLU);
    transpose_w<<<dim3(16, 32), tb>>>(W3, W3T, DGLU, DIM);
    bias_cat<<<6, 256>>>(bf, bi, bg, bcat);

    dim3 blk(128);
    dim3 gD(4, 512), gG(8, 512), gTri(12, 512);
    const int rowsBlocks = MROWS / 8;
    const int scanBlocks = BSZ * SCAN_CH;

    // lam->bA, iraw->bB, g->bC in one launch
    tc_gemm<MODE_TRI, false><<<gTri, blk, SMEM_BYTES>>>(bD, wt, bcat, bA, bB, bC, nullptr, lbp, DIM, DIM);
    scan_pass1<<<scanBlocks, 512>>>(bA, bB, lF, lB, prod, lastF, lastB);
    scan_pass2<<<(BSZ * DIM + 255) / 256, 256>>>(prod, lastF, lastB, CF, CB);
    scan_pass3_rms<<<scanBlocks, 512>>>(bA, lF, lB, CF, CB, bC, bB);   // hg -> bB (rounded)
    tc_gemm<MODE_PLAIN, false><<<gD, blk, SMEM_BYTES>>>(bB, WoT, bo, bD, nullptr, nullptr, nullptr, nullptr, DIM, DIM);
    ln_add<<<rowsBlocks, 256>>>(bD, x, tn_g, tn_b, bC, bA);            // bC = x1, bA = tf32(x1)
    tc_gemm<MODE_PLAIN, false><<<gG, blk, SMEM_BYTES>>>(bA, W2T, b2, bE, nullptr, nullptr, nullptr, nullptr, DGLU, DIM);
    tc_gemm<MODE_GLU,  true><<<gG, blk, SMEM_BYTES>>>(bA, W1T, b1, bF, nullptr, nullptr, bE, nullptr, DGLU, DIM);
    tc_gemm<MODE_PLAIN, false><<<gD, blk, SMEM_BYTES>>>(bF, W3T, b3, bD, nullptr, nullptr, nullptr, nullptr, DIM, DGLU);
    ln_add<<<rowsBlocks, 256>>>(bD, bC, fn_g, fn_b, out, nullptr);
}

// round 7
// speedup vs baseline: 1.6851x; 1.6851x over previous
#include <cuda_runtime.h>
#include <cuda_fp16.h>
#include <math.h>
#include <stdint.h>

#define BSZ 32
#define SEQ 2048
#define DIM 512
#define DGLU 1024
#define MROWS (BSZ * SEQ)
#define SCAN_TS 32
#define SCAN_CH (SEQ / SCAN_TS)

#define HROW 40                 // halves per smem row (32 + 8 pad)
#define TILEH (128 * HROW)      // halves per tile
#define STAGEH (2 * TILEH)
#define SMEM_BYTES (4 * STAGEH * 2)   // 81920 bytes

__device__ float g_bufA[(size_t)MROWS * DIM];
__device__ float g_bufB[(size_t)MROWS * DIM];
__device__ float g_bufC[(size_t)MROWS * DIM];
__device__ float g_bufD[(size_t)MROWS * DIM];
__device__ float g_bufE[(size_t)MROWS * DGLU];
__device__ float g_bufF[(size_t)MROWS * DGLU];
__device__ float g_WT[1312768];   // 2621440 halves (weights) + 1536 floats bias

__device__ __forceinline__ float sigmoidf_(float v) { return 1.f / (1.f + expf(-v)); }

enum { MODE_PLAIN = 0, MODE_GLU = 1, MODE_TRI = 2 };

__device__ __forceinline__ void mma_f16(float* d, const uint32_t* a, const uint32_t* b) {
    asm volatile("mma.sync.aligned.m16n8k16.row.col.f32.f16.f16.f32 "
                 "{%0,%1,%2,%3}, {%4,%5,%6,%7}, {%8,%9}, {%0,%1,%2,%3};"
                 : "+f"(d[0]), "+f"(d[1]), "+f"(d[2]), "+f"(d[3])
                 : "r"(a[0]), "r"(a[1]), "r"(a[2]), "r"(a[3]), "r"(b[0]), "r"(b[1]));
}
__device__ __forceinline__ void cpasync16(uint32_t dst, const void* src) {
    asm volatile("cp.async.cg.shared.global [%0], [%1], 16;" :: "r"(dst), "l"(src));
}
__device__ __forceinline__ uint32_t smem_u32(const void* p) {
    uint32_t a;
    asm("{ .reg .u64 t; cvta.to.shared.u64 t, %1; cvt.u32.u64 %0, t; }" : "=r"(a) : "l"(p));
    return a;
}

// stage one 128x32(half) A tile + B tile
__device__ __forceinline__ void stage_in(uint32_t smem_stage_u, const __half* Ab, const __half* Bb,
                                         int K, int kc, int tid) {
#pragma unroll
    for (int i = 0; i < 4; i++) {
        const int idx = tid + i * 256;          // 0..1023
        const int mat = idx >> 9;               // 0=A, 1=B
        const int r   = (idx >> 2) & 127;
        const int c8  = idx & 3;
        const __half* src = (mat ? Bb : Ab) + (size_t)r * K + kc * 32 + c8 * 8;
        const uint32_t dst = smem_stage_u + (uint32_t)(mat * TILEH + r * HROW + c8 * 8) * 2u;
        cpasync16(dst, src);
    }
}

// C[M,N] = epilogue(A[M,K] @ WT[N,K]^T + bias), A/WT half, acc fp32
// 256 threads, 8 warps 2x4, 64x32 warp tiles, BK=32 halves, 4-stage cp.async.
template <int MODE>
__global__ __launch_bounds__(256)
void tc_gemm(const __half* __restrict__ A, const __half* __restrict__ WT,
             const float* __restrict__ bias, void* __restrict__ Cv,
             float* __restrict__ C1, float* __restrict__ C2,
             const float* __restrict__ aux, const float* __restrict__ lbp, int N, int K)
{
    extern __shared__ __half sm[];

    const int tid = threadIdx.x, wid = tid >> 5, lane = tid & 31;
    const int g = lane >> 2, cc = lane & 3;
    const int bm = blockIdx.y * 128;
    const int wm = (wid >> 2) * 64, wn = (wid & 3) * 32;
    const uint32_t sm_u = smem_u32(sm);

    const __half* Ab = A + (size_t)bm * K;
    const __half* Bb = WT + (size_t)blockIdx.x * 128 * K;
    const int NK = K >> 5;

    float acc[4][4][4];
#pragma unroll
    for (int mf = 0; mf < 4; mf++)
#pragma unroll
        for (int nf = 0; nf < 4; nf++)
#pragma unroll
            for (int k = 0; k < 4; k++) acc[mf][nf][k] = 0.f;

#pragma unroll
    for (int s = 0; s < 3; s++) {
        stage_in(sm_u + s * STAGEH * 2, Ab, Bb, K, s, tid);
        asm volatile("cp.async.commit_group;");
    }

    for (int kc = 0; kc < NK; kc++) {
        asm volatile("cp.async.wait_group 2;");
        __syncthreads();
        if (kc + 3 < NK)
            stage_in(sm_u + ((kc + 3) & 3) * STAGEH * 2, Ab, Bb, K, kc + 3, tid);
        asm volatile("cp.async.commit_group;");

        const __half* As = sm + (kc & 3) * STAGEH;
        const __half* Bs = As + TILEH;
#pragma unroll
        for (int ks = 0; ks < 2; ks++) {
            uint32_t af[4][4], bf[4][2];
#pragma unroll
            for (int mf = 0; mf < 4; mf++) {
                const __half* p = As + (wm + mf * 16 + g) * HROW + ks * 16 + cc * 2;
                af[mf][0] = *(const uint32_t*)(p);
                af[mf][1] = *(const uint32_t*)(p + 8 * HROW);
                af[mf][2] = *(const uint32_t*)(p + 8);
                af[mf][3] = *(const uint32_t*)(p + 8 * HROW + 8);
            }
#pragma unroll
            for (int nf = 0; nf < 4; nf++) {
                const __half* q = Bs + (wn + nf * 8 + g) * HROW + ks * 16 + cc * 2;
                bf[nf][0] = *(const uint32_t*)(q);
                bf[nf][1] = *(const uint32_t*)(q + 8);
            }
#pragma unroll
            for (int mf = 0; mf < 4; mf++)
#pragma unroll
                for (int nf = 0; nf < 4; nf++)
                    mma_f16(acc[mf][nf], af[mf], bf[nf]);
        }
        __syncthreads();
    }

    int seg = 0, bnl = blockIdx.x * 128;
    float* Cout = (float*)Cv;
    float lb = 0.f;
    if (MODE == MODE_TRI) {
        seg = blockIdx.x >> 2;
        bnl = (blockIdx.x & 3) * 128;
        Cout = (seg == 0) ? (float*)Cv : (seg == 1 ? C1 : C2);
        if (seg == 0) lb = __ldg(lbp);
    }

#pragma unroll
    for (int mf = 0; mf < 4; mf++) {
#pragma unroll
        for (int half_ = 0; half_ < 2; half_++) {
            const int row = bm + wm + mf * 16 + g + half_ * 8;
            const float* Arow = (MODE == MODE_GLU) ? aux + (size_t)row * N : nullptr;
#pragma unroll
            for (int nf = 0; nf < 4; nf++) {
                const int col = bnl + wn + nf * 8 + cc * 2;
                const float2 bb = *(const float2*)&bias[blockIdx.x * 128 + wn + nf * 8 + cc * 2];
                float v0 = acc[mf][nf][half_ * 2 + 0] + bb.x;
                float v1 = acc[mf][nf][half_ * 2 + 1] + bb.y;
                float o0 = v0, o1 = v1;
                if (MODE == MODE_TRI) {
                    if (seg == 0) {
                        o0 = lb + (1.f - lb) * sigmoidf_(v0);
                        o1 = lb + (1.f - lb) * sigmoidf_(v1);
                    } else if (seg == 2) {
                        o0 = sigmoidf_(v0); o1 = sigmoidf_(v1);
                    }
                } else if (MODE == MODE_GLU) {
                    const float2 ax = *(const float2*)(Arow + col);
                    o0 = (v0 * sigmoidf_(v0)) * ax.x;
                    o1 = (v1 * sigmoidf_(v1)) * ax.y;
                }
                if (MODE == MODE_GLU) {
                    __half2 h2 = __floats2half2_rn(o0, o1);
                    *(__half2*)((__half*)Cv + (size_t)row * N + col) = h2;
                } else {
                    float2 o; o.x = o0; o.y = o1;
                    *(float2*)(Cout + (size_t)row * N + col) = o;
                }
            }
        }
    }
}

// dst[n*K+k] = half(src[k*N+n])
__global__ void transpose_w(const float* __restrict__ src, __half* __restrict__ dst, int K, int N) {
    __shared__ float tile[32][33];
    const int n0 = blockIdx.x * 32, k0 = blockIdx.y * 32;
    for (int i = threadIdx.y; i < 32; i += 8)
        tile[i][threadIdx.x] = src[(size_t)(k0 + i) * N + n0 + threadIdx.x];
    __syncthreads();
    for (int i = threadIdx.y; i < 32; i += 8)
        dst[(size_t)(n0 + i) * K + k0 + threadIdx.x] = __float2half_rn(tile[threadIdx.x][i]);
}

__global__ void round_xh(const float* __restrict__ src, __half* __restrict__ dst) {
    const size_t i = (size_t)blockIdx.x * blockDim.x + threadIdx.x;
    float4 v = *(const float4*)(src + i * 4);
    __half2 a = __floats2half2_rn(v.x, v.y);
    __half2 b = __floats2half2_rn(v.z, v.w);
    uint2 u; u.x = *(uint32_t*)&a; u.y = *(uint32_t*)&b;
    *(uint2*)(dst + i * 4) = u;
}

__global__ void bias_cat(const float* __restrict__ b0, const float* __restrict__ b1,
                         const float* __restrict__ b2, float* __restrict__ dst) {
    const int i = blockIdx.x * blockDim.x + threadIdx.x;
    if (i < DIM) dst[i] = b0[i];
    else if (i < 2 * DIM) dst[i] = b1[i - DIM];
    else if (i < 3 * DIM) dst[i] = b2[i - 2 * DIM];
}

// pass1 with u = (1-lam)*silu(iraw) inline
__global__ __launch_bounds__(512)
void scan_pass1(const float* __restrict__ lam, const float* __restrict__ iraw,
                float* __restrict__ lF, float* __restrict__ lB,
                float* __restrict__ prod, float* __restrict__ lastF, float* __restrict__ lastB)
{
    const int b = blockIdx.x >> 6, ch = blockIdx.x & 63;
    const int d = threadIdx.x;
    const size_t base = ((size_t)b * SEQ + ch * SCAN_TS) * DIM + d;
    float hf = 0.f, p = 1.f;
#pragma unroll 4
    for (int t = 0; t < SCAN_TS; t++) {
        const size_t ix = base + (size_t)t * DIM;
        const float l = lam[ix], iv = iraw[ix];
        const float u = (1.f - l) * (iv * sigmoidf_(iv));
        hf = fmaf(l, hf, u); p *= l; lF[ix] = hf;
    }
    float hb = 0.f;
#pragma unroll 4
    for (int t = SCAN_TS - 1; t >= 0; t--) {
        const size_t ix = base + (size_t)t * DIM;
        const float l = lam[ix], iv = iraw[ix];
        const float u = (1.f - l) * (iv * sigmoidf_(iv));
        hb = fmaf(l, hb, u); lB[ix] = hb;
    }
    const int ci = (b * SCAN_CH + ch) * DIM + d;
    prod[ci] = p; lastF[ci] = hf; lastB[ci] = hb;
}

__global__ void scan_pass2(const float* __restrict__ prod, const float* __restrict__ lastF,
                           const float* __restrict__ lastB, float* __restrict__ CF, float* __restrict__ CB)
{
    const int c = blockIdx.x * blockDim.x + threadIdx.x;
    if (c >= BSZ * DIM) return;
    const int b = c >> 9, d = c & 511;
    float cf = 0.f;
    for (int ch = 0; ch < SCAN_CH; ch++) {
        const int i = (b * SCAN_CH + ch) * DIM + d;
        CF[i] = cf; cf = fmaf(prod[i], cf, lastF[i]);
    }
    float cb = 0.f;
    for (int ch = SCAN_CH - 1; ch >= 0; ch--) {
        const int i = (b * SCAN_CH + ch) * DIM + d;
        CB[i] = cb; cb = fmaf(prod[i], cb, lastB[i]);
    }
}

__global__ __launch_bounds__(512)
void scan_pass3(const float* __restrict__ lam, const float* __restrict__ lF,
                const float* __restrict__ lB, const float* __restrict__ CF,
                const float* __restrict__ CB, float* __restrict__ h)
{
    const int b = blockIdx.x >> 6, ch = blockIdx.x & 63;
    const int d = threadIdx.x;
    const size_t base = ((size_t)b * SEQ + ch * SCAN_TS) * DIM + d;
    const int ci = (b * SCAN_CH + ch) * DIM + d;
    const float cf = CF[ci], cb = CB[ci];
    float vals[SCAN_TS];
    float p = 1.f;
#pragma unroll
    for (int t = 0; t < SCAN_TS; t++) {
        const size_t ix = base + (size_t)t * DIM;
        p *= lam[ix];
        vals[t] = fmaf(cf, p, lF[ix]);
    }
    float q = 1.f;
#pragma unroll
    for (int t = SCAN_TS - 1; t >= 0; t--) {
        const size_t ix = base + (size_t)t * DIM;
        q *= lam[ix];
        h[ix] = vals[t] + fmaf(cb, q, lB[ix]);
    }
}

// out_half = half(rmsnorm(h) * g)
__global__ void rms_gate(const float* __restrict__ h, const float* __restrict__ g,
                         __half* __restrict__ out) {
    const int row = blockIdx.x * 8 + (threadIdx.x >> 5), lane = threadIdx.x & 31;
    const float* hr = h + (size_t)row * DIM;
    float4 v[4]; float ss = 0.f;
#pragma unroll
    for (int i = 0; i < 4; i++) {
        v[i] = *(const float4*)(hr + i * 128 + lane * 4);
        ss += v[i].x * v[i].x + v[i].y * v[i].y + v[i].z * v[i].z + v[i].w * v[i].w;
    }
#pragma unroll
    for (int o = 16; o > 0; o >>= 1) ss += __shfl_xor_sync(0xffffffffu, ss, o);
    const float sc = rsqrtf(ss * (1.f / DIM) + 1e-6f);
    const float* gr = g + (size_t)row * DIM;
    __half* outr = out + (size_t)row * DIM;
#pragma unroll
    for (int i = 0; i < 4; i++) {
        float4 gv = *(const float4*)(gr + i * 128 + lane * 4);
        __half2 a = __floats2half2_rn(v[i].x * sc * gv.x, v[i].y * sc * gv.y);
        __half2 b = __floats2half2_rn(v[i].z * sc * gv.z, v[i].w * sc * gv.w);
        uint2 u; u.x = *(uint32_t*)&a; u.y = *(uint32_t*)&b;
        *(uint2*)(outr + i * 128 + lane * 4) = u;
    }
}

// out = resid + LN(y)*gam + bet ; optional half copy
__global__ void ln_add(const float* __restrict__ y, const float* __restrict__ resid,
                       const float* __restrict__ gam, const float* __restrict__ bet,
                       float* __restrict__ out, __half* __restrict__ outH) {
    const int row = blockIdx.x * 8 + (threadIdx.x >> 5), lane = threadIdx.x & 31;
    const float* yr = y + (size_t)row * DIM;
    float4 v[4]; float s1 = 0.f, s2 = 0.f;
#pragma unroll
    for (int i = 0; i < 4; i++) {
        v[i] = *(const float4*)(yr + i * 128 + lane * 4);
        s1 += v[i].x + v[i].y + v[i].z + v[i].w;
        s2 += v[i].x * v[i].x + v[i].y * v[i].y + v[i].z * v[i].z + v[i].w * v[i].w;
    }
#pragma unroll
    for (int o = 16; o > 0; o >>= 1) {
        s1 += __shfl_xor_sync(0xffffffffu, s1, o);
        s2 += __shfl_xor_sync(0xffffffffu, s2, o);
    }
    const float mean = s1 * (1.f / DIM);
    const float inv = rsqrtf(s2 * (1.f / DIM) - mean * mean + 1e-5f);
    const float* rr = resid + (size_t)row * DIM;
    float* outr = out + (size_t)row * DIM;
    __half* outh = outH ? outH + (size_t)row * DIM : nullptr;
#pragma unroll
    for (int i = 0; i < 4; i++) {
        const int col = i * 128 + lane * 4;
        float4 gv = *(const float4*)(gam + col);
        float4 bv = *(const float4*)(bet + col);
        float4 xv = *(const float4*)(rr + col);
        float4 r;
        r.x = xv.x + (v[i].x - mean) * inv * gv.x + bv.x;
        r.y = xv.y + (v[i].y - mean) * inv * gv.y + bv.y;
        r.z = xv.z + (v[i].z - mean) * inv * gv.z + bv.z;
        r.w = xv.w + (v[i].w - mean) * inv * gv.w + bv.w;
        *(float4*)(outr + col) = r;
        if (outh) {
            __half2 a = __floats2half2_rn(r.x, r.y);
            __half2 b = __floats2half2_rn(r.z, r.w);
            uint2 u; u.x = *(uint32_t*)&a; u.y = *(uint32_t*)&b;
            *(uint2*)(outh + col) = u;
        }
    }
}

extern "C" void kernel_launch(void* const* d_in, const int* in_sizes, int n_in,
                              void* d_out, int out_size)
{
    const float* x = (const float*)d_in[0];
    const float* lbp = (const float*)d_in[1];
    const float* Wi = (const float*)d_in[2];  const float* bi = (const float*)d_in[3];
    const float* Wf = (const float*)d_in[4];  const float* bf = (const float*)d_in[5];
    const float* Wg = (const float*)d_in[6];  const float* bg = (const float*)d_in[7];
    const float* Wo = (const float*)d_in[8];  const float* bo = (const float*)d_in[9];
    const float* tn_g = (const float*)d_in[10]; const float* tn_b = (const float*)d_in[11];
    const float* fn_g = (const float*)d_in[12]; const float* fn_b = (const float*)d_in[13];
    const float* W1 = (const float*)d_in[14]; const float* b1 = (const float*)d_in[15];
    const float* W2 = (const float*)d_in[16]; const float* b2 = (const float*)d_in[17];
    const float* W3 = (const float*)d_in[18]; const float* b3 = (const float*)d_in[19];
    float* out = (float*)d_out;

    float *bA, *bB, *bC, *bD, *bE, *bF, *wt;
    cudaGetSymbolAddress((void**)&bA, g_bufA);
    cudaGetSymbolAddress((void**)&bB, g_bufB);
    cudaGetSymbolAddress((void**)&bC, g_bufC);
    cudaGetSymbolAddress((void**)&bD, g_bufD);
    cudaGetSymbolAddress((void**)&bE, g_bufE);
    cudaGetSymbolAddress((void**)&bF, g_bufF);
    cudaGetSymbolAddress((void**)&wt, g_WT);

    __half* wh = (__half*)wt;
    __half* WfT = wh;                    // merged rows 0-511
    __half* WiT = wh + 262144;           // rows 512-1023
    __half* WgT = wh + 524288;           // rows 1024-1535
    __half* WoT = wh + 786432;
    __half* W1T = wh + 1048576;
    __half* W2T = wh + 1572864;
    __half* W3T = wh + 2097152;
    float* bcat = wt + 1310720;          // after 2621440 halves

    __half* xh  = (__half*)bD;           // tf16(x); dead after TRI GEMM
    __half* hgh = (__half*)bA;           // rms*g, after lam dead
    __half* x1h = (__half*)bD;           // tf16(x1), after h dead
    __half* ph  = (__half*)bF;           // GLU product, after scan scratch dead

    float* lF = bE;
    float* lB = bF;
    float* prod  = bE + (size_t)MROWS * DIM;
    float* lastF = prod + (size_t)BSZ * SCAN_CH * DIM;
    float* lastB = lastF + (size_t)BSZ * SCAN_CH * DIM;
    float* CF = bF + (size_t)MROWS * DIM;
    float* CB = CF + (size_t)BSZ * SCAN_CH * DIM;

    cudaFuncSetAttribute(tc_gemm<MODE_TRI>,   cudaFuncAttributeMaxDynamicSharedMemorySize, SMEM_BYTES);
    cudaFuncSetAttribute(tc_gemm<MODE_PLAIN>, cudaFuncAttributeMaxDynamicSharedMemorySize, SMEM_BYTES);
    cudaFuncSetAttribute(tc_gemm<MODE_GLU>,   cudaFuncAttributeMaxDynamicSharedMemorySize, SMEM_BYTES);

    dim3 tb(32, 8);
    round_xh<<<32768, 256>>>(x, xh);
    transpose_w<<<dim3(16, 16), tb>>>(Wf, WfT, DIM, DIM);
    transpose_w<<<dim3(16, 16), tb>>>(Wi, WiT, DIM, DIM);
    transpose_w<<<dim3(16, 16), tb>>>(Wg, WgT, DIM, DIM);
    transpose_w<<<dim3(16, 16), tb>>>(Wo, WoT, DIM, DIM);
    transpose_w<<<dim3(32, 16), tb>>>(W1, W1T, DIM, DGLU);
    transpose_w<<<dim3(32, 16), tb>>>(W2, W2T, DIM, DGLU);
    transpose_w<<<dim3(16, 32), tb>>>(W3, W3T, DGLU, DIM);
    bias_cat<<<6, 256>>>(bf, bi, bg, bcat);

    dim3 blk(256);
    dim3 gD(4, 512), gG(8, 512), gTri(12, 512);
    const int rowsBlocks = MROWS / 8;
    const int scanBlocks = BSZ * SCAN_CH;

    // lam->bA, iraw->bB, g->bC
    tc_gemm<MODE_TRI><<<gTri, blk, SMEM_BYTES>>>(xh, wh, bcat, bA, bB, bC, nullptr, lbp, DIM, DIM);
    scan_pass1<<<scanBlocks, 512>>>(bA, bB, lF, lB, prod, lastF, lastB);
    scan_pass2<<<(BSZ * DIM + 255) / 256, 256>>>(prod, lastF, lastB, CF, CB);
    scan_pass3<<<scanBlocks, 512>>>(bA, lF, lB, CF, CB, bD + 0);   // h -> bD (xh dead)
    rms_gate<<<rowsBlocks, 256>>>(bD, bC, hgh);                    // hg(half) -> bA
    tc_gemm<MODE_PLAIN><<<gD, blk, SMEM_BYTES>>>(hgh, WoT, bo, bB, nullptr, nullptr, nullptr, nullptr, DIM, DIM);
    ln_add<<<rowsBlocks, 256>>>(bB, x, tn_g, tn_b, bC, x1h);       // bC = x1, bD = half(x1)
    tc_gemm<MODE_PLAIN><<<gG, blk, SMEM_BYTES>>>(x1h, W2T, b2, bE, nullptr, nullptr, nullptr, nullptr, DGLU, DIM);
    tc_gemm<MODE_GLU><<<gG, blk, SMEM_BYTES>>>(x1h, W1T, b1, ph, nullptr, nullptr, bE, nullptr, DGLU, DIM);
    tc_gemm<MODE_PLAIN><<<gD, blk, SMEM_BYTES>>>(ph, W3T, b3, bB, nullptr, nullptr, nullptr, nullptr, DIM, DGLU);
    ln_add<<<rowsBlocks, 256>>>(bB, bC, fn_g, fn_b, out, nullptr);
}